// round 9
// baseline (speedup 1.0000x reference)
#include <cuda_runtime.h>
#include <math.h>

#define BSZ     64
#define NF      16
#define NFILT   32
#define KTAP    8
#define LSEQ    16384
#define THRV    0.25f
#define BETA    15.0f
#define TCH     128
#define WUP     40          // alpha^40 ~ 1.6e-6: boundary error << tolerance
#define NCHUNK  (LSEQ / TCH)
#define TBUF    32
#define PITCH   33
#define WPB     4

// ---- packed f32x2 helpers (Blackwell FFMA2; PTX-only, ptxas won't auto-fuse) ----
__device__ __forceinline__ unsigned long long pk2(float lo, float hi) {
    unsigned long long r;
    asm("mov.b64 %0, {%1,%2};" : "=l"(r) : "f"(lo), "f"(hi));
    return r;
}
__device__ __forceinline__ void upk2(unsigned long long p, float& lo, float& hi) {
    asm("mov.b64 {%0,%1}, %2;" : "=f"(lo), "=f"(hi) : "l"(p));
}
__device__ __forceinline__ unsigned long long fma2(unsigned long long a,
                                                   unsigned long long b,
                                                   unsigned long long c) {
    unsigned long long d;
    asm("fma.rn.f32x2 %0, %1, %2, %3;" : "=l"(d) : "l"(a), "l"(b), "l"(c));
    return d;
}

// one warp per (b, chunk); lane = filter index 0..31
__global__ __launch_bounds__(WPB * 32, 10)
void snn_scan_kernel(const float* __restrict__ x,
                     const float* __restrict__ wa,
                     const float* __restrict__ wb,
                     const float* __restrict__ ta,
                     const float* __restrict__ tb,
                     float* __restrict__ out)
{
    __shared__ float buf[WPB][NFILT][PITCH];   // v_pre per (f, t mod 32)

    const int warp_global = (blockIdx.x * blockDim.x + threadIdx.x) >> 5;
    const int w    = (threadIdx.x >> 5);
    const int lane = threadIdx.x & 31;
    if (warp_global >= BSZ * NCHUNK) return;

    const int b     = warp_global / NCHUNK;
    const int chunk = warp_global % NCHUNK;
    const int f     = lane;
    const int ch    = f >> 4;

    // ---- per-filter constants ----
    const float* wsrc = (ch == 0) ? (wa + f * KTAP) : (wb + (f - NF) * KTAP);
    float wgt[KTAP];
    float ss = 0.f;
    #pragma unroll
    for (int k = 0; k < KTAP; k++) { wgt[k] = wsrc[k]; ss = __fmaf_rn(wgt[k], wgt[k], ss); }
    const float inv = 1.0f / fmaxf(sqrtf(ss), 1e-8f);
    unsigned long long w2[KTAP];               // {w, w} packed
    #pragma unroll
    for (int k = 0; k < KTAP; k++) {
        const float wn = __fmul_rn(wgt[k], inv);
        w2[k] = pk2(wn, wn);
    }

    const float raw   = (ch == 0) ? ta[f] : tb[f - NF];
    const float sp    = fmaxf(raw, 0.f) + log1pf(expf(-fabsf(raw)));   // softplus
    const float tau   = sp + 1e-4f;
    const float alpha = expf(-1.0f / tau);
    const float oma   = 1.0f - alpha;

    const float* xb = x + (size_t)(b * 2 + ch) * LSEQ;

    const int t0   = chunk * TCH;
    const int wlen = (chunk == 0) ? 0 : WUP;
    const int ts   = t0 - wlen;

    // ---- packed sliding window: PS[i] = {c[i+1], c[i+2]}, i=0..5; carry = c[7] ----
    unsigned long long PS[6];
    float carry;
    if (chunk == 0) {
        #pragma unroll
        for (int i = 0; i < 6; i++) PS[i] = 0ULL;   // {+0,+0}
        carry = 0.f;
    } else {
        const float4 h0 = *(const float4*)(xb + ts - 8);
        const float4 h1 = *(const float4*)(xb + ts - 4);
        float h[8] = {h0.x, h0.y, h0.z, h0.w, h1.x, h1.y, h1.z, h1.w};
        #pragma unroll
        for (int i = 0; i < 6; i++) PS[i] = pk2(h[i + 1], h[i + 2]);
        carry = h[7];
    }

    // vp-form recurrence (exact): vp_t = spike_{t-1} ? d_t : fma(alpha, vp_{t-1}, d_t)
    float vp = 0.f;
    bool  spike = false;

    // ---- phase 1: warm-up (no outputs) ----
    for (int g = 0; g < wlen; g += 4) {
        const float4 n = *(const float4*)(xb + ts + g);
        const unsigned long long P7  = pk2(carry, n.x);
        const unsigned long long P8  = pk2(n.x, n.y);
        const unsigned long long P9  = pk2(n.y, n.z);
        const unsigned long long P10 = pk2(n.z, n.w);
        unsigned long long A = fma2(w2[0], PS[0], 0ULL);
        A = fma2(w2[1], PS[1], A); A = fma2(w2[2], PS[2], A);
        A = fma2(w2[3], PS[3], A); A = fma2(w2[4], PS[4], A);
        A = fma2(w2[5], PS[5], A); A = fma2(w2[6], P7, A); A = fma2(w2[7], P8, A);
        unsigned long long Bp = fma2(w2[0], PS[2], 0ULL);
        Bp = fma2(w2[1], PS[3], Bp); Bp = fma2(w2[2], PS[4], Bp);
        Bp = fma2(w2[3], PS[5], Bp); Bp = fma2(w2[4], P7, Bp);
        Bp = fma2(w2[5], P8, Bp);  Bp = fma2(w2[6], P9, Bp); Bp = fma2(w2[7], P10, Bp);
        float I0, I1, I2, I3;
        upk2(A, I0, I1); upk2(Bp, I2, I3);
        float dd[4];
        dd[0] = __fmul_rn(oma, I0); dd[1] = __fmul_rn(oma, I1);
        dd[2] = __fmul_rn(oma, I2); dd[3] = __fmul_rn(oma, I3);
        #pragma unroll
        for (int j = 0; j < 4; j++) {
            const float fmares = __fmaf_rn(alpha, vp, dd[j]);
            vp    = spike ? dd[j] : fmares;
            spike = (vp >= THRV);
        }
        PS[0] = PS[4]; PS[1] = PS[5]; PS[2] = P7; PS[3] = P8; PS[4] = P9; PS[5] = P10;
        carry = n.w;
    }

    const size_t plane = (size_t)BSZ * NFILT * LSEQ;
    const size_t bbase = (size_t)b * NFILT * LSEQ;

    // ---- phase 2: main scan, buffered + whole-line write-through flush ----
    for (int tile = 0; tile < TCH / TBUF; ++tile) {
        const int tbase = t0 + tile * TBUF;

        #pragma unroll
        for (int g = 0; g < TBUF; g += 4) {
            const float4 n = *(const float4*)(xb + tbase + g);
            const unsigned long long P7  = pk2(carry, n.x);
            const unsigned long long P8  = pk2(n.x, n.y);
            const unsigned long long P9  = pk2(n.y, n.z);
            const unsigned long long P10 = pk2(n.z, n.w);
            unsigned long long A = fma2(w2[0], PS[0], 0ULL);
            A = fma2(w2[1], PS[1], A); A = fma2(w2[2], PS[2], A);
            A = fma2(w2[3], PS[3], A); A = fma2(w2[4], PS[4], A);
            A = fma2(w2[5], PS[5], A); A = fma2(w2[6], P7, A); A = fma2(w2[7], P8, A);
            unsigned long long Bp = fma2(w2[0], PS[2], 0ULL);
            Bp = fma2(w2[1], PS[3], Bp); Bp = fma2(w2[2], PS[4], Bp);
            Bp = fma2(w2[3], PS[5], Bp); Bp = fma2(w2[4], P7, Bp);
            Bp = fma2(w2[5], P8, Bp);  Bp = fma2(w2[6], P9, Bp); Bp = fma2(w2[7], P10, Bp);
            float I0, I1, I2, I3;
            upk2(A, I0, I1); upk2(Bp, I2, I3);
            float dd[4];
            dd[0] = __fmul_rn(oma, I0); dd[1] = __fmul_rn(oma, I1);
            dd[2] = __fmul_rn(oma, I2); dd[3] = __fmul_rn(oma, I3);

            #pragma unroll
            for (int j = 0; j < 4; j++) {
                const float fmares = __fmaf_rn(alpha, vp, dd[j]);
                vp = spike ? dd[j] : fmares;
                spike = (vp >= THRV);
                buf[w][lane][g + j] = vp;          // STS.32: (lane+t)%32 conflict-free
            }
            PS[0] = PS[4]; PS[1] = PS[5]; PS[2] = P7; PS[3] = P8; PS[4] = P9; PS[5] = P10;
            carry = n.w;
        }

        __syncwarp();

        // ---- flush: 4 filters x 128B per STG.128, whole lines, write-through ----
        {
            const int fr   = lane >> 3;            // 0..3: filter within group
            const int tseg = (lane & 7) << 2;      // 0,4,...,28: 16B segment
            #pragma unroll
            for (int rb = 0; rb < NFILT; rb += 4) {
                const int ff = rb + fr;
                const float v0 = buf[w][ff][tseg + 0];
                const float v1 = buf[w][ff][tseg + 1];
                const float v2 = buf[w][ff][tseg + 2];
                const float v3 = buf[w][ff][tseg + 3];
                const float4 v4 = make_float4(v0, v1, v2, v3);
                const float4 z4 = make_float4(__fmul_rn(BETA, __fadd_rn(v0, -THRV)),
                                              __fmul_rn(BETA, __fadd_rn(v1, -THRV)),
                                              __fmul_rn(BETA, __fadd_rn(v2, -THRV)),
                                              __fmul_rn(BETA, __fadd_rn(v3, -THRV)));
                const float4 s4 = make_float4(v0 >= THRV ? 1.f : 0.f,
                                              v1 >= THRV ? 1.f : 0.f,
                                              v2 >= THRV ? 1.f : 0.f,
                                              v3 >= THRV ? 1.f : 0.f);
                float* p = out + (bbase + (size_t)ff * LSEQ + tbase + tseg);
                __stwt((float4*)p, v4);
                __stwt((float4*)(p + plane), z4);
                __stwt((float4*)(p + 2 * plane), s4);
            }

            // logits: lane = t; tree max over 32 filters (conflict-free LDS)
            float m0 = buf[w][0][lane], m1 = buf[w][1][lane];
            float m2 = buf[w][2][lane], m3 = buf[w][3][lane];
            #pragma unroll
            for (int i = 4; i < NFILT; i += 4) {
                m0 = fmaxf(m0, buf[w][i + 0][lane]);
                m1 = fmaxf(m1, buf[w][i + 1][lane]);
                m2 = fmaxf(m2, buf[w][i + 2][lane]);
                m3 = fmaxf(m3, buf[w][i + 3][lane]);
            }
            const float vmax = fmaxf(fmaxf(m0, m1), fmaxf(m2, m3));
            // max_f z == z(max_f vp) exactly (z monotone under RN)
            __stwt(out + 3 * plane + (size_t)b * LSEQ + tbase + lane,
                   __fmul_rn(BETA, __fadd_rn(vmax, -THRV)));
        }

        __syncwarp();
    }
}

extern "C" void kernel_launch(void* const* d_in, const int* in_sizes, int n_in,
                              void* d_out, int out_size)
{
    const float* x  = (const float*)d_in[0];
    const float* wa = (const float*)d_in[1];
    const float* wb = (const float*)d_in[2];
    const float* ta = (const float*)d_in[3];
    const float* tb = (const float*)d_in[4];
    float* out = (float*)d_out;

    // 8192 warps: one per (b, chunk); 4 warps/block -> 2048 blocks
    const int total_warps = BSZ * NCHUNK;
    const int threads = WPB * 32;
    const int blocks  = (total_warps * 32) / threads;
    snn_scan_kernel<<<blocks, threads>>>(x, wa, wb, ta, tb, out);
}

// round 10
// speedup vs baseline: 1.1392x; 1.1392x over previous
#include <cuda_runtime.h>
#include <math.h>

#define BSZ     64
#define NF      16
#define NFILT   32
#define KTAP    8
#define LSEQ    16384
#define THRV    0.25f
#define BETA    15.0f
#define TCH     128
#define WUP     48          // validated best (R6/R7/R8); R9's 40 raised rel_err
#define NCHUNK  (LSEQ / TCH)
#define TBUF    32
#define PITCH   33
#define WPB     4

// ---- packed f32x2 helpers (Blackwell FFMA2; PTX-only, ptxas won't auto-fuse) ----
__device__ __forceinline__ unsigned long long pk2(float lo, float hi) {
    unsigned long long r;
    asm("mov.b64 %0, {%1,%2};" : "=l"(r) : "f"(lo), "f"(hi));
    return r;
}
__device__ __forceinline__ void upk2(unsigned long long p, float& lo, float& hi) {
    asm("mov.b64 {%0,%1}, %2;" : "=f"(lo), "=f"(hi) : "l"(p));
}
__device__ __forceinline__ unsigned long long fma2(unsigned long long a,
                                                   unsigned long long b,
                                                   unsigned long long c) {
    unsigned long long d;
    asm("fma.rn.f32x2 %0, %1, %2, %3;" : "=l"(d) : "l"(a), "l"(b), "l"(c));
    return d;
}

// z = BETA*(vp - THR) as one FFMA: 15*vp - 3.75 (<=1ulp vs two-op form; monotone in vp)
__device__ __forceinline__ float zfma(float vp) {
    return __fmaf_rn(BETA, vp, -BETA * THRV);
}

// one warp per (b, chunk); lane = filter index 0..31
__global__ __launch_bounds__(WPB * 32, 10)
void snn_scan_kernel(const float* __restrict__ x,
                     const float* __restrict__ wa,
                     const float* __restrict__ wb,
                     const float* __restrict__ ta,
                     const float* __restrict__ tb,
                     float* __restrict__ out)
{
    __shared__ float buf[WPB][NFILT][PITCH];   // v_pre per (f, t mod 32)

    const int warp_global = (blockIdx.x * blockDim.x + threadIdx.x) >> 5;
    const int w    = (threadIdx.x >> 5);
    const int lane = threadIdx.x & 31;
    if (warp_global >= BSZ * NCHUNK) return;

    const int b     = warp_global / NCHUNK;
    const int chunk = warp_global % NCHUNK;
    const int f     = lane;
    const int ch    = f >> 4;

    // ---- per-filter constants ----
    const float* wsrc = (ch == 0) ? (wa + f * KTAP) : (wb + (f - NF) * KTAP);
    float wgt[KTAP];
    float ss = 0.f;
    #pragma unroll
    for (int k = 0; k < KTAP; k++) { wgt[k] = wsrc[k]; ss = __fmaf_rn(wgt[k], wgt[k], ss); }
    const float inv = 1.0f / fmaxf(sqrtf(ss), 1e-8f);
    unsigned long long w2[KTAP];               // {w, w} packed
    #pragma unroll
    for (int k = 0; k < KTAP; k++) {
        const float wn = __fmul_rn(wgt[k], inv);
        w2[k] = pk2(wn, wn);
    }

    const float raw   = (ch == 0) ? ta[f] : tb[f - NF];
    const float sp    = fmaxf(raw, 0.f) + log1pf(expf(-fabsf(raw)));   // softplus
    const float tau   = sp + 1e-4f;
    const float alpha = expf(-1.0f / tau);
    const float oma   = 1.0f - alpha;

    const float* xb = x + (size_t)(b * 2 + ch) * LSEQ;

    const int t0   = chunk * TCH;
    const int wlen = (chunk == 0) ? 0 : WUP;
    const int ts   = t0 - wlen;

    // ---- packed sliding window: PS[i] = {c[i+1], c[i+2]}, i=0..5; carry = c[7] ----
    unsigned long long PS[6];
    float carry;
    if (chunk == 0) {
        #pragma unroll
        for (int i = 0; i < 6; i++) PS[i] = 0ULL;   // {+0,+0}
        carry = 0.f;
    } else {
        const float4 h0 = *(const float4*)(xb + ts - 8);
        const float4 h1 = *(const float4*)(xb + ts - 4);
        float h[8] = {h0.x, h0.y, h0.z, h0.w, h1.x, h1.y, h1.z, h1.w};
        #pragma unroll
        for (int i = 0; i < 6; i++) PS[i] = pk2(h[i + 1], h[i + 2]);
        carry = h[7];
    }

    // vp-form recurrence (exact): vp_t = spike_{t-1} ? d_t : fma(alpha, vp_{t-1}, d_t)
    float vp = 0.f;
    bool  spike = false;

    // ---- phase 1: warm-up (no outputs) ----
    for (int g = 0; g < wlen; g += 4) {
        const float4 n = *(const float4*)(xb + ts + g);
        const unsigned long long P7  = pk2(carry, n.x);
        const unsigned long long P8  = pk2(n.x, n.y);
        const unsigned long long P9  = pk2(n.y, n.z);
        const unsigned long long P10 = pk2(n.z, n.w);
        unsigned long long A = fma2(w2[0], PS[0], 0ULL);
        A = fma2(w2[1], PS[1], A); A = fma2(w2[2], PS[2], A);
        A = fma2(w2[3], PS[3], A); A = fma2(w2[4], PS[4], A);
        A = fma2(w2[5], PS[5], A); A = fma2(w2[6], P7, A); A = fma2(w2[7], P8, A);
        unsigned long long Bp = fma2(w2[0], PS[2], 0ULL);
        Bp = fma2(w2[1], PS[3], Bp); Bp = fma2(w2[2], PS[4], Bp);
        Bp = fma2(w2[3], PS[5], Bp); Bp = fma2(w2[4], P7, Bp);
        Bp = fma2(w2[5], P8, Bp);  Bp = fma2(w2[6], P9, Bp); Bp = fma2(w2[7], P10, Bp);
        float I0, I1, I2, I3;
        upk2(A, I0, I1); upk2(Bp, I2, I3);
        float dd[4];
        dd[0] = __fmul_rn(oma, I0); dd[1] = __fmul_rn(oma, I1);
        dd[2] = __fmul_rn(oma, I2); dd[3] = __fmul_rn(oma, I3);
        #pragma unroll
        for (int j = 0; j < 4; j++) {
            const float fmares = __fmaf_rn(alpha, vp, dd[j]);
            vp    = spike ? dd[j] : fmares;
            spike = (vp >= THRV);
        }
        PS[0] = PS[4]; PS[1] = PS[5]; PS[2] = P7; PS[3] = P8; PS[4] = P9; PS[5] = P10;
        carry = n.w;
    }

    const size_t plane = (size_t)BSZ * NFILT * LSEQ;
    const size_t bbase = (size_t)b * NFILT * LSEQ;

    // ---- phase 2: main scan, buffered + whole-line streaming flush ----
    for (int tile = 0; tile < TCH / TBUF; ++tile) {
        const int tbase = t0 + tile * TBUF;

        #pragma unroll
        for (int g = 0; g < TBUF; g += 4) {
            const float4 n = *(const float4*)(xb + tbase + g);
            const unsigned long long P7  = pk2(carry, n.x);
            const unsigned long long P8  = pk2(n.x, n.y);
            const unsigned long long P9  = pk2(n.y, n.z);
            const unsigned long long P10 = pk2(n.z, n.w);
            unsigned long long A = fma2(w2[0], PS[0], 0ULL);
            A = fma2(w2[1], PS[1], A); A = fma2(w2[2], PS[2], A);
            A = fma2(w2[3], PS[3], A); A = fma2(w2[4], PS[4], A);
            A = fma2(w2[5], PS[5], A); A = fma2(w2[6], P7, A); A = fma2(w2[7], P8, A);
            unsigned long long Bp = fma2(w2[0], PS[2], 0ULL);
            Bp = fma2(w2[1], PS[3], Bp); Bp = fma2(w2[2], PS[4], Bp);
            Bp = fma2(w2[3], PS[5], Bp); Bp = fma2(w2[4], P7, Bp);
            Bp = fma2(w2[5], P8, Bp);  Bp = fma2(w2[6], P9, Bp); Bp = fma2(w2[7], P10, Bp);
            float I0, I1, I2, I3;
            upk2(A, I0, I1); upk2(Bp, I2, I3);
            float dd[4];
            dd[0] = __fmul_rn(oma, I0); dd[1] = __fmul_rn(oma, I1);
            dd[2] = __fmul_rn(oma, I2); dd[3] = __fmul_rn(oma, I3);

            #pragma unroll
            for (int j = 0; j < 4; j++) {
                const float fmares = __fmaf_rn(alpha, vp, dd[j]);
                vp = spike ? dd[j] : fmares;
                spike = (vp >= THRV);
                buf[w][lane][g + j] = vp;          // STS.32: (lane+t)%32 conflict-free
            }
            PS[0] = PS[4]; PS[1] = PS[5]; PS[2] = P7; PS[3] = P8; PS[4] = P9; PS[5] = P10;
            carry = n.w;
        }

        __syncwarp();

        // ---- flush: 4 filters x 128B per STG.128, whole lines, streaming ----
        {
            const int fr   = lane >> 3;            // 0..3: filter within group
            const int tseg = (lane & 7) << 2;      // 0,4,...,28: 16B segment
            #pragma unroll
            for (int rb = 0; rb < NFILT; rb += 4) {
                const int ff = rb + fr;
                const float v0 = buf[w][ff][tseg + 0];
                const float v1 = buf[w][ff][tseg + 1];
                const float v2 = buf[w][ff][tseg + 2];
                const float v3 = buf[w][ff][tseg + 3];
                const float4 v4 = make_float4(v0, v1, v2, v3);
                const float4 z4 = make_float4(zfma(v0), zfma(v1), zfma(v2), zfma(v3));
                const float4 s4 = make_float4(v0 >= THRV ? 1.f : 0.f,
                                              v1 >= THRV ? 1.f : 0.f,
                                              v2 >= THRV ? 1.f : 0.f,
                                              v3 >= THRV ? 1.f : 0.f);
                float* p = out + (bbase + (size_t)ff * LSEQ + tbase + tseg);
                __stcs((float4*)p, v4);
                __stcs((float4*)(p + plane), z4);
                __stcs((float4*)(p + 2 * plane), s4);
            }

            // logits: lane = t; tree max over 32 filters (conflict-free LDS)
            float m0 = buf[w][0][lane], m1 = buf[w][1][lane];
            float m2 = buf[w][2][lane], m3 = buf[w][3][lane];
            #pragma unroll
            for (int i = 4; i < NFILT; i += 4) {
                m0 = fmaxf(m0, buf[w][i + 0][lane]);
                m1 = fmaxf(m1, buf[w][i + 1][lane]);
                m2 = fmaxf(m2, buf[w][i + 2][lane]);
                m3 = fmaxf(m3, buf[w][i + 3][lane]);
            }
            const float vmax = fmaxf(fmaxf(m0, m1), fmaxf(m2, m3));
            // max_f z == z(max_f vp): FFMA monotone in vp (positive multiplier)
            __stcs(out + 3 * plane + (size_t)b * LSEQ + tbase + lane, zfma(vmax));
        }

        __syncwarp();
    }
}

extern "C" void kernel_launch(void* const* d_in, const int* in_sizes, int n_in,
                              void* d_out, int out_size)
{
    const float* x  = (const float*)d_in[0];
    const float* wa = (const float*)d_in[1];
    const float* wb = (const float*)d_in[2];
    const float* ta = (const float*)d_in[3];
    const float* tb = (const float*)d_in[4];
    float* out = (float*)d_out;

    // 8192 warps: one per (b, chunk); 4 warps/block -> 2048 blocks
    const int total_warps = BSZ * NCHUNK;
    const int threads = WPB * 32;
    const int blocks  = (total_warps * 32) / threads;
    snn_scan_kernel<<<blocks, threads>>>(x, wa, wb, ta, tb, out);
}